// round 3
// baseline (speedup 1.0000x reference)
#include <cuda_runtime.h>
#include <cstdint>

// Problem constants (fixed by reference setup_inputs)
#define BB 8
#define NN 50000
#define CC 80
#define MAXDET 100
#define NPROB (BB * CC)          // 640 independent NMS problems
#define CAP 2048                 // candidate buffer per problem (expect ~500 @ T0)
#define T0 0.99f                 // gather threshold (uniform scores -> ~500 cands)
#define SCORE_T 0.05f
#define NMS_T 0.5f
#define TOTDET (CC * MAXDET)     // 8000 per batch

#define NEG_INF __int_as_float(0xff800000)

// ---------------- device-global scratch (no allocations allowed) -------------
__device__ int                g_count[NPROB];
__device__ int                g_flag[NPROB];
__device__ unsigned long long g_cand[NPROB * CAP];
__device__ int                g_nms_idx[NPROB * MAXDET];
__device__ float              g_nms_score[NPROB * MAXDET];
__device__ float              g_fb_scores[(size_t)NPROB * NN];   // fallback scratch (~128MB, rarely touched)

// Order-preserving float<->uint mapping (total order, -inf smallest)
__device__ __forceinline__ unsigned int ord_of(float f) {
    unsigned int u = __float_as_uint(f);
    return (u & 0x80000000u) ? ~u : (u | 0x80000000u);
}
__device__ __forceinline__ float float_of_ord(unsigned int o) {
    unsigned int u = (o & 0x80000000u) ? (o & 0x7FFFFFFFu) : ~o;
    return __uint_as_float(u);
}

// ---------------- kernel 1: zero counters --------------------------------
__global__ void k_zero() {
    int i = blockIdx.x * blockDim.x + threadIdx.x;
    if (i < NPROB) { g_count[i] = 0; g_flag[i] = 0; }
}

// ---------------- kernel 2: coalesced candidate gather -------------------
// classification layout: [B, N, C] float32, C=80 -> 20 float4 per (b,n) row.
__global__ void k_gather(const float* __restrict__ cls) {
    unsigned int i4 = blockIdx.x * blockDim.x + threadIdx.x;
    const unsigned int TOT4 = (unsigned int)BB * NN * (CC / 4);   // 8,000,000
    if (i4 >= TOT4) return;
    float4 v = reinterpret_cast<const float4*>(cls)[i4];
    unsigned int c4  = i4 % (CC / 4);          // 32-bit const-div -> mul.hi
    unsigned int rem = i4 / (CC / 4);
    unsigned int n   = rem % NN;
    unsigned int b   = rem / NN;
    float vv[4] = {v.x, v.y, v.z, v.w};
#pragma unroll
    for (int k = 0; k < 4; k++) {
        if (vv[k] > T0) {
            int p = (int)(b * CC + c4 * 4 + k);
            int pos = atomicAdd(&g_count[p], 1);
            if (pos < CAP) {
                // key: score (descending) major, anchor index (ascending) minor
                unsigned long long key =
                    ((unsigned long long)ord_of(vv[k]) << 32) |
                    (unsigned int)(~n);
                g_cand[p * CAP + pos] = key;
            }
        }
    }
}

// ---------------- kernel 3: per-(b,c) sort + lazy greedy NMS -------------
__global__ void k_nms(const float* __restrict__ boxes) {
    __shared__ unsigned long long sk[CAP];
    __shared__ float sx1[MAXDET], sy1[MAXDET], sx2[MAXDET], sy2[MAXDET], sar[MAXDET];

    int p = blockIdx.x;
    int b = p / CC;
    int cnt = g_count[p];
    if (cnt > CAP) {                       // overflow -> exact fallback handles it
        if (threadIdx.x == 0) g_flag[p] = 1;
        return;
    }
    for (int i = threadIdx.x; i < CAP; i += blockDim.x)
        sk[i] = (i < cnt) ? g_cand[p * CAP + i] : 0ULL;
    __syncthreads();

    // bitonic sort, descending (k==CAP final pass: all blocks descending)
    for (int k = 2; k <= CAP; k <<= 1) {
        for (int j = k >> 1; j > 0; j >>= 1) {
            for (int t = threadIdx.x; t < CAP; t += blockDim.x) {
                int ixj = t ^ j;
                if (ixj > t) {
                    unsigned long long a = sk[t], c2 = sk[ixj];
                    bool desc = ((t & k) == 0);
                    if (desc ? (a < c2) : (a > c2)) { sk[t] = c2; sk[ixj] = a; }
                }
            }
            __syncthreads();
        }
    }

    // warp 0: sequential greedy, lane-parallel IoU vs selected set
    if (threadIdx.x < 32) {
        int lane = threadIdx.x;
        int S = 0;
        const float* bx = boxes + (long long)b * NN * 4;
        for (int i = 0; i < cnt && S < MAXDET; i++) {
            unsigned long long key = sk[i];
            int idx = (int)(~(unsigned int)key);
            float4 bb;
            if (lane == 0) bb = reinterpret_cast<const float4*>(bx)[idx];
            bb.x = __shfl_sync(0xffffffffu, bb.x, 0);
            bb.y = __shfl_sync(0xffffffffu, bb.y, 0);
            bb.z = __shfl_sync(0xffffffffu, bb.z, 0);
            bb.w = __shfl_sync(0xffffffffu, bb.w, 0);
            float area = (bb.z - bb.x) * (bb.w - bb.y);
            bool sup = false;
            for (int j = lane; j < S; j += 32) {
                float ix1 = fmaxf(bb.x, sx1[j]);
                float iy1 = fmaxf(bb.y, sy1[j]);
                float ix2 = fminf(bb.z, sx2[j]);
                float iy2 = fminf(bb.w, sy2[j]);
                float inter = fmaxf(ix2 - ix1, 0.0f) * fmaxf(iy2 - iy1, 0.0f);
                float uni = area + sar[j] - inter;
                float iou = inter / fmaxf(uni, 1e-8f);
                if (iou > NMS_T) sup = true;
            }
            sup = __any_sync(0xffffffffu, sup);
            if (!sup) {
                if (lane == 0) {
                    sx1[S] = bb.x; sy1[S] = bb.y; sx2[S] = bb.z; sy2[S] = bb.w; sar[S] = area;
                    g_nms_idx[p * MAXDET + S] = idx;
                    g_nms_score[p * MAXDET + S] = float_of_ord((unsigned int)(key >> 32));
                }
                S++;
            }
        }
        if (lane == 0 && S < MAXDET) g_flag[p] = 1;  // might need scores <= T0 -> exact fallback
    }
}

// ---------------- kernel 4: exact fallback (expected never to fire) ------
__global__ void k_fallback(const float* __restrict__ boxes, const float* __restrict__ cls) {
    int p = blockIdx.x;
    if (!g_flag[p]) return;
    int b = p / CC, c = p % CC;
    float* s = g_fb_scores + (size_t)p * NN;
    for (int i = threadIdx.x; i < NN; i += blockDim.x) {
        float v = cls[((long long)b * NN + i) * CC + c];
        s[i] = (v > SCORE_T) ? v : NEG_INF;
    }
    __syncthreads();

    __shared__ float sx1[MAXDET], sy1[MAXDET], sx2[MAXDET], sy2[MAXDET], sar[MAXDET];
    __shared__ unsigned long long red[8];
    __shared__ unsigned long long s_best;
    __shared__ int s_sup;

    int S = 0;
    const float* bx = boxes + (long long)b * NN * 4;
    int lane = threadIdx.x & 31;

    for (;;) {
        // block argmax over N scores, tie -> lowest index (key embeds ~idx)
        unsigned long long best = 0;
        for (int i = threadIdx.x; i < NN; i += blockDim.x) {
            unsigned long long k2 = ((unsigned long long)ord_of(s[i]) << 32) |
                                    (unsigned int)(~(unsigned int)i);
            if (k2 > best) best = k2;
        }
        for (int o = 16; o; o >>= 1) {
            unsigned long long t = __shfl_down_sync(0xffffffffu, best, o);
            if (t > best) best = t;
        }
        if (lane == 0) red[threadIdx.x >> 5] = best;
        __syncthreads();
        if (threadIdx.x < 32) {
            best = (threadIdx.x < (blockDim.x >> 5)) ? red[threadIdx.x] : 0ULL;
            for (int o = 16; o; o >>= 1) {
                unsigned long long t = __shfl_down_sync(0xffffffffu, best, o);
                if (t > best) best = t;
            }
            if (threadIdx.x == 0) s_best = best;
        }
        __syncthreads();
        best = s_best;
        float sc = float_of_ord((unsigned int)(best >> 32));
        if (!(sc > NEG_INF)) break;             // all remaining are -inf
        int idx = (int)(~(unsigned int)best);

        if (threadIdx.x < 32) {
            float4 bb;
            if (lane == 0) bb = reinterpret_cast<const float4*>(bx)[idx];
            bb.x = __shfl_sync(0xffffffffu, bb.x, 0);
            bb.y = __shfl_sync(0xffffffffu, bb.y, 0);
            bb.z = __shfl_sync(0xffffffffu, bb.z, 0);
            bb.w = __shfl_sync(0xffffffffu, bb.w, 0);
            float area = (bb.z - bb.x) * (bb.w - bb.y);
            bool sup = false;
            for (int j = lane; j < S; j += 32) {
                float ix1 = fmaxf(bb.x, sx1[j]);
                float iy1 = fmaxf(bb.y, sy1[j]);
                float ix2 = fminf(bb.z, sx2[j]);
                float iy2 = fminf(bb.w, sy2[j]);
                float inter = fmaxf(ix2 - ix1, 0.0f) * fmaxf(iy2 - iy1, 0.0f);
                float uni = area + sar[j] - inter;
                float iou = inter / fmaxf(uni, 1e-8f);
                if (iou > NMS_T) sup = true;
            }
            sup = __any_sync(0xffffffffu, sup);
            if (lane == 0) {
                if (!sup) {
                    sx1[S] = bb.x; sy1[S] = bb.y; sx2[S] = bb.z; sy2[S] = bb.w; sar[S] = area;
                    g_nms_idx[p * MAXDET + S] = idx;
                    g_nms_score[p * MAXDET + S] = sc;
                }
                s_sup = sup ? 1 : 0;
            }
        }
        __syncthreads();
        if (!s_sup) S++;
        if (threadIdx.x == 0) s[idx] = NEG_INF;
        __syncthreads();
        if (S >= MAXDET) break;
    }
    __syncthreads();
    for (int m = S + threadIdx.x; m < MAXDET; m += blockDim.x) {
        g_nms_idx[p * MAXDET + m] = NN;          // dummy anchor
        g_nms_score[p * MAXDET + m] = NEG_INF;
    }
}

// ---------------- kernel 5: per-batch top-100 over 8000 -------------------
// Key: score desc major, flat position asc minor -> matches lax.top_k stability.
__global__ void k_topk(const float* __restrict__ boxes, float* __restrict__ out) {
    extern __shared__ unsigned long long sk2[];   // 8192 keys = 64KB
    const int SZ = 8192;
    int b = blockIdx.x;
    for (int i = threadIdx.x; i < SZ; i += blockDim.x) {
        if (i < TOTDET) {
            float sc = g_nms_score[b * TOTDET + i];
            sk2[i] = ((unsigned long long)ord_of(sc) << 32) | (unsigned int)(8191 - i);
        } else {
            sk2[i] = 0ULL;
        }
    }
    __syncthreads();
    for (int k = 2; k <= SZ; k <<= 1) {
        for (int j = k >> 1; j > 0; j >>= 1) {
            for (int t = threadIdx.x; t < SZ; t += blockDim.x) {
                int ixj = t ^ j;
                if (ixj > t) {
                    unsigned long long a = sk2[t], c2 = sk2[ixj];
                    bool desc = ((t & k) == 0);
                    if (desc ? (a < c2) : (a > c2)) { sk2[t] = c2; sk2[ixj] = a; }
                }
            }
            __syncthreads();
        }
    }
    if (threadIdx.x < MAXDET) {
        int j = threadIdx.x;
        unsigned long long k2 = sk2[j];
        int pos = 8191 - (int)(k2 & 0xFFFFFFFFull);
        float sc = float_of_ord((unsigned int)(k2 >> 32));
        int idx = g_nms_idx[b * TOTDET + pos];
        float4 bb = make_float4(0.f, 0.f, 0.f, 0.f);
        float label = -1.0f;
        if (idx < NN) {
            bb = reinterpret_cast<const float4*>(boxes + (long long)b * NN * 4)[idx];
            label = (float)(pos / MAXDET);
        }
        // output layout (float32): boxes [8,100,4] | scores [8,100] | labels [8,100]
        float* ob = out;
        float* os = out + BB * MAXDET * 4;
        float* ol = out + BB * MAXDET * 4 + BB * MAXDET;
        reinterpret_cast<float4*>(ob)[b * MAXDET + j] = bb;
        os[b * MAXDET + j] = sc;
        ol[b * MAXDET + j] = label;
    }
}

// ---------------- launch ---------------------------------------------------
extern "C" void kernel_launch(void* const* d_in, const int* in_sizes, int n_in,
                              void* d_out, int out_size) {
    const float* boxes = (const float*)d_in[0];          // [8, 50000, 4]
    const float* cls   = (const float*)d_in[1];          // [8, 50000, 80]
    float* out = (float*)d_out;

    cudaFuncSetAttribute(k_topk, cudaFuncAttributeMaxDynamicSharedMemorySize, 8192 * 8);

    k_zero<<<10, 64>>>();
    unsigned int tot4 = (unsigned int)BB * NN * (CC / 4);   // 8,000,000 float4
    int gblocks = (int)((tot4 + 511) / 512);
    k_gather<<<gblocks, 512>>>(cls);
    k_nms<<<NPROB, 512>>>(boxes);
    k_fallback<<<NPROB, 256>>>(boxes, cls);
    k_topk<<<BB, 1024, 8192 * 8>>>(boxes, out);
}

// round 9
// speedup vs baseline: 1.5290x; 1.5290x over previous
#include <cuda_runtime.h>
#include <cstdint>

// Problem constants (fixed by reference setup_inputs)
#define BB 8
#define NN 50000
#define CC 80
#define MAXDET 100
#define NPROB (BB * CC)          // 640 independent NMS problems
#define CAP 2048                 // candidate buffer per problem (expect ~500 @ T0)
#define T0 0.99f                 // gather threshold (uniform scores -> ~500 cands)
#define SCORE_T 0.05f
#define NMS_T 0.5f
#define TOTDET (CC * MAXDET)     // 8000 per batch
#define PF 256                   // boxes prefetched into smem for greedy phase

#define NEG_INF __int_as_float(0xff800000)

// ---------------- device-global scratch (no allocations allowed) -------------
__device__ int                g_count[NPROB];
__device__ int                g_flag[NPROB];
__device__ unsigned long long g_cand[NPROB * CAP];
__device__ int                g_nms_idx[NPROB * MAXDET];
__device__ float              g_nms_score[NPROB * MAXDET];
__device__ float              g_fb_scores[(size_t)NPROB * NN];   // fallback scratch (rarely touched)

// Order-preserving float<->uint mapping (total order, -inf smallest)
__device__ __forceinline__ unsigned int ord_of(float f) {
    unsigned int u = __float_as_uint(f);
    return (u & 0x80000000u) ? ~u : (u | 0x80000000u);
}
__device__ __forceinline__ float float_of_ord(unsigned int o) {
    unsigned int u = (o & 0x80000000u) ? (o & 0x7FFFFFFFu) : ~o;
    return __uint_as_float(u);
}

// ---------------- kernel 1: zero counters --------------------------------
__global__ void k_zero() {
    int i = blockIdx.x * blockDim.x + threadIdx.x;
    if (i < NPROB) { g_count[i] = 0; g_flag[i] = 0; }
}

// ---------------- kernel 2: coalesced candidate gather -------------------
// classification layout: [B, N, C] float32, C=80 -> 20 float4 per (b,n) row.
__global__ void k_gather(const float* __restrict__ cls) {
    unsigned int i4 = blockIdx.x * blockDim.x + threadIdx.x;
    const unsigned int TOT4 = (unsigned int)BB * NN * (CC / 4);   // 8,000,000
    if (i4 >= TOT4) return;
    float4 v = reinterpret_cast<const float4*>(cls)[i4];
    unsigned int c4  = i4 % (CC / 4);
    unsigned int rem = i4 / (CC / 4);
    unsigned int n   = rem % NN;
    unsigned int b   = rem / NN;
    float vv[4] = {v.x, v.y, v.z, v.w};
#pragma unroll
    for (int k = 0; k < 4; k++) {
        if (vv[k] > T0) {
            int p = (int)(b * CC + c4 * 4 + k);
            int pos = atomicAdd(&g_count[p], 1);
            if (pos < CAP) {
                // key: score (descending) major, anchor index (ascending) minor
                unsigned long long key =
                    ((unsigned long long)ord_of(vv[k]) << 32) |
                    (unsigned int)(~n);
                g_cand[p * CAP + pos] = key;
            }
        }
    }
}

// ---------------- kernel 3: per-(b,c) adaptive sort + lazy greedy NMS ------
__global__ void k_nms(const float* __restrict__ boxes) {
    __shared__ unsigned long long sk[CAP];
    __shared__ float4 s_box[PF];
    __shared__ float  s_area[PF];
    __shared__ float sx1[MAXDET], sy1[MAXDET], sx2[MAXDET], sy2[MAXDET], sar[MAXDET];

    int p = blockIdx.x;
    int b = p / CC;
    int cnt = g_count[p];
    if (cnt > CAP || cnt == 0) {           // overflow / empty -> exact fallback
        if (threadIdx.x == 0) g_flag[p] = 1;
        return;
    }

    // adaptive power-of-two sort size (typically 512 for cnt~500)
    int SZ = 2;
    while (SZ < cnt) SZ <<= 1;

    for (int i = threadIdx.x; i < SZ; i += blockDim.x)
        sk[i] = (i < cnt) ? g_cand[p * CAP + i] : 0ULL;
    __syncthreads();

    // bitonic sort, descending
    for (int k = 2; k <= SZ; k <<= 1) {
        for (int j = k >> 1; j > 0; j >>= 1) {
            for (int t = threadIdx.x; t < SZ; t += blockDim.x) {
                int ixj = t ^ j;
                if (ixj > t) {
                    unsigned long long a = sk[t], c2 = sk[ixj];
                    bool desc = ((t & k) == 0);
                    if (desc ? (a < c2) : (a > c2)) { sk[t] = c2; sk[ixj] = a; }
                }
            }
            __syncthreads();
        }
    }

    // cooperative high-MLP prefetch of the first P candidates' boxes
    const float* bx = boxes + (long long)b * NN * 4;
    int P = min(cnt, PF);
    for (int i = threadIdx.x; i < P; i += blockDim.x) {
        int idx = (int)(~(unsigned int)sk[i]);
        float4 bb = reinterpret_cast<const float4*>(bx)[idx];
        s_box[i] = bb;
        s_area[i] = (bb.z - bb.x) * (bb.w - bb.y);
    }
    __syncthreads();

    // warp 0: sequential greedy, lane-parallel IoU vs selected set
    if (threadIdx.x < 32) {
        int lane = threadIdx.x;
        int S = 0;
        for (int i = 0; i < cnt && S < MAXDET; i++) {
            unsigned long long key = sk[i];
            float4 bb;
            float area;
            if (i < P) {                       // broadcast LDS, no shfl needed
                bb = s_box[i];
                area = s_area[i];
            } else {                           // rare slow path
                int idx = (int)(~(unsigned int)key);
                if (lane == 0) bb = reinterpret_cast<const float4*>(bx)[idx];
                bb.x = __shfl_sync(0xffffffffu, bb.x, 0);
                bb.y = __shfl_sync(0xffffffffu, bb.y, 0);
                bb.z = __shfl_sync(0xffffffffu, bb.z, 0);
                bb.w = __shfl_sync(0xffffffffu, bb.w, 0);
                area = (bb.z - bb.x) * (bb.w - bb.y);
            }
            bool sup = false;
            for (int j = lane; j < S; j += 32) {
                float ix1 = fmaxf(bb.x, sx1[j]);
                float iy1 = fmaxf(bb.y, sy1[j]);
                float ix2 = fminf(bb.z, sx2[j]);
                float iy2 = fminf(bb.w, sy2[j]);
                float inter = fmaxf(ix2 - ix1, 0.0f) * fmaxf(iy2 - iy1, 0.0f);
                float uni = area + sar[j] - inter;
                float iou = inter / fmaxf(uni, 1e-8f);
                if (iou > NMS_T) sup = true;
            }
            sup = __any_sync(0xffffffffu, sup);
            if (!sup) {
                if (lane == 0) {
                    sx1[S] = bb.x; sy1[S] = bb.y; sx2[S] = bb.z; sy2[S] = bb.w; sar[S] = area;
                    int idx = (int)(~(unsigned int)key);
                    g_nms_idx[p * MAXDET + S] = idx;
                    g_nms_score[p * MAXDET + S] = float_of_ord((unsigned int)(key >> 32));
                }
                S++;
            }
        }
        if (lane == 0 && S < MAXDET) g_flag[p] = 1;  // may need scores <= T0 -> exact fallback
    }
}

// ---------------- kernel 4: exact fallback (expected never to fire) ------
__global__ void k_fallback(const float* __restrict__ boxes, const float* __restrict__ cls) {
    int p = blockIdx.x;
    if (!g_flag[p]) return;
    int b = p / CC, c = p % CC;
    float* s = g_fb_scores + (size_t)p * NN;
    for (int i = threadIdx.x; i < NN; i += blockDim.x) {
        float v = cls[((long long)b * NN + i) * CC + c];
        s[i] = (v > SCORE_T) ? v : NEG_INF;
    }
    __syncthreads();

    __shared__ float sx1[MAXDET], sy1[MAXDET], sx2[MAXDET], sy2[MAXDET], sar[MAXDET];
    __shared__ unsigned long long red[8];
    __shared__ unsigned long long s_best;
    __shared__ int s_sup;

    int S = 0;
    const float* bx = boxes + (long long)b * NN * 4;
    int lane = threadIdx.x & 31;

    for (;;) {
        unsigned long long best = 0;
        for (int i = threadIdx.x; i < NN; i += blockDim.x) {
            unsigned long long k2 = ((unsigned long long)ord_of(s[i]) << 32) |
                                    (unsigned int)(~(unsigned int)i);
            if (k2 > best) best = k2;
        }
        for (int o = 16; o; o >>= 1) {
            unsigned long long t = __shfl_down_sync(0xffffffffu, best, o);
            if (t > best) best = t;
        }
        if (lane == 0) red[threadIdx.x >> 5] = best;
        __syncthreads();
        if (threadIdx.x < 32) {
            best = (threadIdx.x < (blockDim.x >> 5)) ? red[threadIdx.x] : 0ULL;
            for (int o = 16; o; o >>= 1) {
                unsigned long long t = __shfl_down_sync(0xffffffffu, best, o);
                if (t > best) best = t;
            }
            if (threadIdx.x == 0) s_best = best;
        }
        __syncthreads();
        best = s_best;
        float sc = float_of_ord((unsigned int)(best >> 32));
        if (!(sc > NEG_INF)) break;
        int idx = (int)(~(unsigned int)best);

        if (threadIdx.x < 32) {
            float4 bb;
            if (lane == 0) bb = reinterpret_cast<const float4*>(bx)[idx];
            bb.x = __shfl_sync(0xffffffffu, bb.x, 0);
            bb.y = __shfl_sync(0xffffffffu, bb.y, 0);
            bb.z = __shfl_sync(0xffffffffu, bb.z, 0);
            bb.w = __shfl_sync(0xffffffffu, bb.w, 0);
            float area = (bb.z - bb.x) * (bb.w - bb.y);
            bool sup = false;
            for (int j = lane; j < S; j += 32) {
                float ix1 = fmaxf(bb.x, sx1[j]);
                float iy1 = fmaxf(bb.y, sy1[j]);
                float ix2 = fminf(bb.z, sx2[j]);
                float iy2 = fminf(bb.w, sy2[j]);
                float inter = fmaxf(ix2 - ix1, 0.0f) * fmaxf(iy2 - iy1, 0.0f);
                float uni = area + sar[j] - inter;
                float iou = inter / fmaxf(uni, 1e-8f);
                if (iou > NMS_T) sup = true;
            }
            sup = __any_sync(0xffffffffu, sup);
            if (lane == 0) {
                if (!sup) {
                    sx1[S] = bb.x; sy1[S] = bb.y; sx2[S] = bb.z; sy2[S] = bb.w; sar[S] = area;
                    g_nms_idx[p * MAXDET + S] = idx;
                    g_nms_score[p * MAXDET + S] = sc;
                }
                s_sup = sup ? 1 : 0;
            }
        }
        __syncthreads();
        if (!s_sup) S++;
        if (threadIdx.x == 0) s[idx] = NEG_INF;
        __syncthreads();
        if (S >= MAXDET) break;
    }
    __syncthreads();
    for (int m = S + threadIdx.x; m < MAXDET; m += blockDim.x) {
        g_nms_idx[p * MAXDET + m] = NN;          // dummy anchor
        g_nms_score[p * MAXDET + m] = NEG_INF;
    }
}

// ---------------- kernel 5: per-batch top-100 via 80-way tournament merge ---
// Each class list of 100 is already sorted descending by the full 64-bit key
// (score desc major, (8191 - flatpos) minor), so global top-100 = 100 pops of
// an 80-way max. Warp 0 keeps all heads in registers (3 classes per lane).
// Identical comparator to lax.top_k stability; keys are distinct.
__global__ void k_topk(const float* __restrict__ boxes, float* __restrict__ out) {
    extern __shared__ unsigned long long sh[];
    unsigned long long* skeys = sh;                  // [TOTDET] = 8000 keys (64KB)
    int* swin = (int*)(sh + TOTDET);                 // [MAXDET] winning flat positions
    int b = blockIdx.x;
    int tid = threadIdx.x;                           // 256 threads

    for (int i = tid; i < TOTDET; i += blockDim.x) {
        float sc = g_nms_score[b * TOTDET + i];
        skeys[i] = ((unsigned long long)ord_of(sc) << 32) | (unsigned int)(8191 - i);
    }
    __syncthreads();

    if (tid < 32) {
        int lane = tid;
        // heads for classes lane, lane+32, lane+64 (lane+64 valid only for lane<16)
        unsigned long long h0 = skeys[lane * MAXDET];
        unsigned long long h1 = skeys[(lane + 32) * MAXDET];
        unsigned long long h2 = (lane + 64 < CC) ? skeys[(lane + 64) * MAXDET] : 0ULL;
        for (int j = 0; j < MAXDET; j++) {
            unsigned long long v = h0; int vc = lane;
            if (h1 > v) { v = h1; vc = lane + 32; }
            if (h2 > v) { v = h2; vc = lane + 64; }
            for (int o = 16; o; o >>= 1) {
                unsigned long long v2 = __shfl_down_sync(0xffffffffu, v, o);
                int vc2 = __shfl_down_sync(0xffffffffu, vc, o);
                if (v2 > v) { v = v2; vc = vc2; }
            }
            vc = __shfl_sync(0xffffffffu, vc, 0);
            if (lane == (vc & 31)) {                 // owner advances its head
                int slot = vc >> 5;
                unsigned long long cur = (slot == 0) ? h0 : ((slot == 1) ? h1 : h2);
                int pos = 8191 - (int)(unsigned int)cur;
                swin[j] = pos;
                unsigned long long nk = (((pos + 1) % MAXDET) != 0) ? skeys[pos + 1] : 0ULL;
                if (slot == 0) h0 = nk; else if (slot == 1) h1 = nk; else h2 = nk;
            }
        }
    }
    __syncthreads();

    // parallel epilogue: 100 threads fetch boxes and write outputs
    if (tid < MAXDET) {
        int j = tid;
        int pos = swin[j];
        unsigned long long key = skeys[pos];
        float sc = float_of_ord((unsigned int)(key >> 32));
        int idx = g_nms_idx[b * TOTDET + pos];
        float4 bb = make_float4(0.f, 0.f, 0.f, 0.f);
        float label = -1.0f;
        if (idx < NN) {
            bb = reinterpret_cast<const float4*>(boxes + (long long)b * NN * 4)[idx];
            label = (float)(pos / MAXDET);
        }
        // output layout (float32): boxes [8,100,4] | scores [8,100] | labels [8,100]
        float* ob = out;
        float* os = out + BB * MAXDET * 4;
        float* ol = out + BB * MAXDET * 4 + BB * MAXDET;
        reinterpret_cast<float4*>(ob)[b * MAXDET + j] = bb;
        os[b * MAXDET + j] = sc;
        ol[b * MAXDET + j] = label;
    }
}

// ---------------- launch ---------------------------------------------------
extern "C" void kernel_launch(void* const* d_in, const int* in_sizes, int n_in,
                              void* d_out, int out_size) {
    const float* boxes = (const float*)d_in[0];          // [8, 50000, 4]
    const float* cls   = (const float*)d_in[1];          // [8, 50000, 80]
    float* out = (float*)d_out;

    const int topk_smem = TOTDET * 8 + MAXDET * 4;       // 64,400 bytes
    cudaFuncSetAttribute(k_topk, cudaFuncAttributeMaxDynamicSharedMemorySize, topk_smem);

    k_zero<<<10, 64>>>();
    unsigned int tot4 = (unsigned int)BB * NN * (CC / 4);   // 8,000,000 float4
    int gblocks = (int)((tot4 + 511) / 512);
    k_gather<<<gblocks, 512>>>(cls);
    k_nms<<<NPROB, 512>>>(boxes);
    k_fallback<<<NPROB, 256>>>(boxes, cls);
    k_topk<<<BB, 256, topk_smem>>>(boxes, out);
}